// round 4
// baseline (speedup 1.0000x reference)
#include <cuda_runtime.h>
#include <cstdint>

typedef unsigned long long u64;
typedef unsigned int u32;

#define N_ENT   50000
#define N_EDGES 800000
#define NQ      (N_EDGES/4)   // 200000 int4-quads
#define D_PE    16
#define NB      784           // NB*NT = 200704 >= NQ : every thread <=1 quad
#define NT      256
#define NTHR    (NB*NT)
#define NW64    782           // ceil(N_ENT/64)
#define NW32    1564

// ---- device state (no allocations allowed) --------------------------------
__device__ ulonglong2 g_state[N_ENT];   // .x = frontier bits, .y = visited bits
__device__ u64 g_next[N_ENT];
__device__ u64 g_cnt[N_ENT];            // packed byte counts c0|c1<<8|c2<<16|c3<<24
__device__ u32 g_Fbm[NW32];             // frontier-nonempty bitmap
__device__ ulonglong2 g_dummy;          // safe target for filtered (dead) loads
__device__ int g_nvalid;
__device__ u32 g_bar_count = 0;
__device__ u32 g_bar_sense = 0;         // monotonic across replays

__device__ __forceinline__ void gbar(u32 base, u32 k) {
    __syncthreads();
    if (threadIdx.x == 0) {
        __threadfence();
        if (atomicInc(&g_bar_count, NB - 1) == NB - 1) {
            *(volatile u32*)&g_bar_sense = base + k;
        } else {
            while ((u32)(*(volatile u32*)&g_bar_sense - base) < k) __nanosleep(64);
        }
    }
    __syncthreads();
}

__device__ __forceinline__ ulonglong2 ldcg128(const ulonglong2* p) {
    ulonglong2 r;
    asm volatile("ld.global.cg.v2.u64 {%0,%1}, [%2];"
                 : "=l"(r.x), "=l"(r.y) : "l"(p));
    return r;
}

// Two edges, branch-free gathers (address-select), conditional RED.OR only.
__device__ __forceinline__ void edge2(const u32* sF, int s0, int d0, int s1, int d1) {
    u32 f0s = (sF[s0 >> 5] >> (s0 & 31)) & 1u;
    u32 f0d = (sF[d0 >> 5] >> (d0 & 31)) & 1u;
    u32 f1s = (sF[s1 >> 5] >> (s1 & 31)) & 1u;
    u32 f1d = (sF[d1 >> 5] >> (d1 & 31)) & 1u;
    const ulonglong2* pA0 = (f0s | f0d) ? &g_state[s0] : &g_dummy;
    const ulonglong2* pB0 = (f0s | f0d) ? &g_state[d0] : &g_dummy;
    const ulonglong2* pA1 = (f1s | f1d) ? &g_state[s1] : &g_dummy;
    const ulonglong2* pB1 = (f1s | f1d) ? &g_state[d1] : &g_dummy;
    ulonglong2 A0 = ldcg128(pA0);       // 4 independent LDG.128 -> MLP
    ulonglong2 B0 = ldcg128(pB0);
    ulonglong2 A1 = ldcg128(pA1);
    ulonglong2 B1 = ldcg128(pB1);
    if (f0s) { u64 nb = A0.x & ~B0.y; if (nb) atomicOr(&g_next[d0], nb); }
    if (f0d) { u64 nb = B0.x & ~A0.y; if (nb) atomicOr(&g_next[s0], nb); }
    if (f1s) { u64 nb = A1.x & ~B1.y; if (nb) atomicOr(&g_next[d1], nb); }
    if (f1d) { u64 nb = B1.x & ~A1.y; if (nb) atomicOr(&g_next[s1], nb); }
}

__global__ void __launch_bounds__(NT, 6)
bfs_all(const int* __restrict__ h, const int* __restrict__ t,
        const int* __restrict__ aidx, const float* __restrict__ embed,
        float* __restrict__ out)
{
    __shared__ u32   sF[NW32];
    __shared__ float sE[6 * D_PE];
    __shared__ int   svals[64];

    const int tid  = threadIdx.x;
    const int blk  = blockIdx.x;
    const int gtid = blk * NT + tid;
    const u32 base = *(volatile u32*)&g_bar_sense;  // stable until barrier 1

    // ---------------- phase A: zero + seed (one barrier total) -------------
    if (gtid < N_ENT) {                  // node gtid owned by block gtid>>8
        g_state[gtid] = make_ulonglong2(0ull, 0ull);
        g_next[gtid]  = 0ull;
        g_cnt[gtid]   = 0ull;
    }
    if (tid < 8) {                       // Fbm word w owned by block w>>3
        int w = blk * 8 + tid;
        if (w < NW32) g_Fbm[w] = 0u;
    }
    if (gtid == 0) g_dummy = make_ulonglong2(0ull, 0ull);
    if (tid < 6 * D_PE) sE[tid] = __ldg(embed + tid);
    if (tid < 64) {                      // every block loads seed candidates
        int e = __ldg(aidx + (tid & 31));
        svals[tid] = (tid < 32) ? __ldg(h + e) : __ldg(t + e);
    }
    __syncthreads();                     // orders zeroing before seed writes
    if (tid < 64) {
        int v = svals[tid];
        bool uniq = true;
        for (int j = 0; j < tid; j++) if (svals[j] == v) uniq = false;
        if (uniq) {
            if ((v >> 8) == blk) {       // owner block writes (in-block ordered)
                u64 bit = 1ull << tid;
                g_state[v] = make_ulonglong2(bit, bit);
                g_cnt[v]   = 1ull;
                atomicOr(&g_Fbm[v >> 5], 1u << (v & 31));
            }
            if (blk == 0) {
                // count uniques: warp-ballot over 2 warps
            }
        }
        if (blk == 0) {
            u32 bal = __ballot_sync(0xffffffffu, uniq);
            if ((tid & 31) == 0) atomicAdd(&g_nvalid, (int)__popc(bal) - ((tid == 0) ? 0 : 0));
        }
    }
    // g_nvalid must be reset per replay: block 0 tid 0 pre-clears via trick:
    // (we instead compute it fresh: clear before the adds in this same phase)
    // -> handled by: tid 255 of block 0 clears BEFORE __syncthreads above.
    gbar(base, 1);

    // ---------------- BFS rounds (depth 1..4; depth 5 provably a no-op) ----
    u32 k = 1;
    #pragma unroll 1
    for (int depth = 1; depth <= 4; ++depth) {
        for (int i = tid; i < NW32; i += NT) sF[i] = __ldcg(&g_Fbm[i]);
        __syncthreads();

        if (gtid < NQ) {
            int4 S = __ldg((const int4*)h + gtid);
            int4 D = __ldg((const int4*)t + gtid);
            edge2(sF, S.x, D.x, S.y, D.y);
            edge2(sF, S.z, D.z, S.w, D.w);
        }
        gbar(base, ++k);

        if (depth < 4) {
            const int gw   = gtid >> 5;
            const int lane = tid & 31;
            const int shift = 8 * depth;
            if (gw < NW64) {
                int n0 = gw * 64 + lane, n1 = n0 + 32;
                u64 nw0 = 0, nw1 = 0;
                if (n0 < N_ENT) {
                    u64 nf = __ldcg(&g_next[n0]);
                    if (nf) {
                        g_next[n0] = 0ull;
                        u64 v = __ldcg(&g_state[n0].y);
                        nw0 = nf & ~v;
                        if (nw0) {
                            g_state[n0] = make_ulonglong2(nw0, v | nw0);
                            g_cnt[n0]  += (u64)__popcll(nw0) << shift;
                        }
                    }
                }
                if (n1 < N_ENT) {
                    u64 nf = __ldcg(&g_next[n1]);
                    if (nf) {
                        g_next[n1] = 0ull;
                        u64 v = __ldcg(&g_state[n1].y);
                        nw1 = nf & ~v;
                        if (nw1) {
                            g_state[n1] = make_ulonglong2(nw1, v | nw1);
                            g_cnt[n1]  += (u64)__popcll(nw1) << shift;
                        }
                    }
                }
                u32 blo = __ballot_sync(0xffffffffu, nw0 != 0);
                u32 bhi = __ballot_sync(0xffffffffu, nw1 != 0);
                if (lane == 0) { g_Fbm[2*gw] = blo; g_Fbm[2*gw + 1] = bhi; }
            }
            gbar(base, ++k);
        }
    }

    // ---------------- final: depth-4 count + embedding combine -------------
    const int nv = *(volatile int*)&g_nvalid;
    const float inv = 1.0f / (float)nv;
    if (gtid < N_ENT) {
        int n = gtid;
        u64 nf = __ldcg(&g_next[n]);
        u64 v  = __ldcg(&g_state[n].y);
        u64 c  = __ldcg(&g_cnt[n]);
        int c4 = __popcll(nf & ~v);
        int c0 = (int)( c        & 0xFF);
        int c1 = (int)((c >> 8)  & 0xFF);
        int c2 = (int)((c >> 16) & 0xFF);
        int c3 = (int)((c >> 24) & 0xFF);
        int rem = nv - (c0 + c1 + c2 + c3 + c4);
        float w0 = c0 * inv, w1 = c1 * inv, w2 = c2 * inv;
        float w3 = c3 * inv, w4 = c4 * inv, w5 = rem * inv;

        float4* o = (float4*)(out + (size_t)n * D_PE);
        #pragma unroll
        for (int q = 0; q < 4; q++) {
            float4 r;
            int b = q * 4;
            r.x = w0*sE[b+0] + w1*sE[D_PE+b+0] + w2*sE[2*D_PE+b+0]
                + w3*sE[3*D_PE+b+0] + w4*sE[4*D_PE+b+0] + w5*sE[5*D_PE+b+0];
            r.y = w0*sE[b+1] + w1*sE[D_PE+b+1] + w2*sE[2*D_PE+b+1]
                + w3*sE[3*D_PE+b+1] + w4*sE[4*D_PE+b+1] + w5*sE[5*D_PE+b+1];
            r.z = w0*sE[b+2] + w1*sE[D_PE+b+2] + w2*sE[2*D_PE+b+2]
                + w3*sE[3*D_PE+b+2] + w4*sE[4*D_PE+b+2] + w5*sE[5*D_PE+b+2];
            r.w = w0*sE[b+3] + w1*sE[D_PE+b+3] + w2*sE[2*D_PE+b+3]
                + w3*sE[3*D_PE+b+3] + w4*sE[4*D_PE+b+3] + w5*sE[5*D_PE+b+3];
            o[q] = r;
        }
    }
}

// Small kernel to reset g_nvalid before the main kernel each call (keeps the
// redundant-seed counting race-free and replay-deterministic).
__global__ void k_reset() { g_nvalid = 0; }

// ---------------------------------------------------------------------------
extern "C" void kernel_launch(void* const* d_in, const int* in_sizes, int n_in,
                              void* d_out, int out_size) {
    const int*   h     = (const int*)d_in[0];
    const int*   t     = (const int*)d_in[1];
    const int*   aidx  = (const int*)d_in[2];
    const float* embed = (const float*)d_in[4];
    float*       out   = (float*)d_out;

    k_reset<<<1, 1>>>();
    bfs_all<<<NB, NT>>>(h, t, aidx, embed, out);
}

// round 5
// speedup vs baseline: 1.8021x; 1.8021x over previous
#include <cuda_runtime.h>
#include <cstdint>

typedef unsigned long long u64;
typedef unsigned int u32;

#define N_ENT   50000
#define N_EDGES 800000
#define D_PE    16
#define NW32    1564        // ceil(50000/32) rounded to even

// ---- device state (no allocations allowed) --------------------------------
__device__ ulonglong2 g_state[N_ENT];   // .x = frontier bits, .y = visited bits
__device__ u64 g_next[N_ENT];
__device__ u64 g_cnt[N_ENT];            // packed byte counts c0|c1<<8|c2<<16|c3<<24
__device__ u32 g_Fbm[NW32];             // frontier-nonempty bitmap (rounds 1-2 only)
__device__ int g_nvalid;

__device__ __forceinline__ ulonglong2 ldcg128(const ulonglong2* p) {
    ulonglong2 r;
    asm volatile("ld.global.cg.v2.u64 {%0,%1}, [%2];"
                 : "=l"(r.x), "=l"(r.y) : "l"(p));
    return r;
}

// ---------------------------------------------------------------------------
// Zero all state + seed anchors. Seeds are written by the block that OWNS the
// node (blk == v>>8), after that block's __syncthreads -> ordered vs zeroing.
// All blocks redundantly compute the 64 seed candidates; block 0 stores nvalid.
__global__ void k_init(const int* __restrict__ h, const int* __restrict__ t,
                       const int* __restrict__ aidx) {
    __shared__ int svals[64];
    __shared__ int scnt;
    const int tid  = threadIdx.x;
    const int blk  = blockIdx.x;
    const int gtid = blk * 256 + tid;

    if (gtid < N_ENT) {
        g_state[gtid] = make_ulonglong2(0ull, 0ull);
        g_next[gtid]  = 0ull;
        g_cnt[gtid]   = 0ull;
    }
    if (tid < 8) {
        int w = blk * 8 + tid;
        if (w < NW32) g_Fbm[w] = 0u;
    }
    if (tid == 0) scnt = 0;
    if (tid < 64) {
        int e = __ldg(aidx + (tid & 31));
        svals[tid] = (tid < 32) ? __ldg(h + e) : __ldg(t + e);
    }
    __syncthreads();
    if (tid < 64) {
        int v = svals[tid];
        bool uniq = true;
        for (int j = 0; j < tid; j++) if (svals[j] == v) uniq = false;
        if (uniq) {
            if ((v >> 8) == blk) {          // owner block writes, ordered by sync
                u64 bit = 1ull << tid;
                g_state[v] = make_ulonglong2(bit, bit);
                g_cnt[v]   = 1ull;
                atomicOr(&g_Fbm[v >> 5], 1u << (v & 31));
            }
            if (blk == 0) atomicAdd(&scnt, 1);
        }
    }
    __syncthreads();
    if (blk == 0 && tid == 0) g_nvalid = scnt;
}

// ---------------------------------------------------------------------------
// Sparse propagation (rounds 1-2): smem bitmap gates everything; almost all
// edges cost only two coalesced reads + two LDS bit tests.
__global__ void __launch_bounds__(512)
k_prop_gated(const int* __restrict__ h, const int* __restrict__ t) {
    __shared__ u32 sF[NW32];
    const int tid = threadIdx.x;
    for (int i = tid; i < NW32; i += 512) sF[i] = __ldcg(&g_Fbm[i]);
    __syncthreads();
    int i = blockIdx.x * 512 + tid;
    if (i >= N_EDGES) return;
    int s = __ldg(h + i);
    int d = __ldg(t + i);
    u32 fS = (sF[s >> 5] >> (s & 31)) & 1u;
    u32 fD = (sF[d >> 5] >> (d & 31)) & 1u;
    if (fS | fD) {
        ulonglong2 Ss = ldcg128(&g_state[s]);
        ulonglong2 Sd = ldcg128(&g_state[d]);
        if (fS) { u64 nb = Ss.x & ~Sd.y; if (nb) atomicOr(&g_next[d], nb); }
        if (fD) { u64 nb = Sd.x & ~Ss.y; if (nb) atomicOr(&g_next[s], nb); }
    }
}

// Dense propagation (rounds 3-4): >=92% of edges are live -> no bitmap; one
// 16B gather per endpoint, dedup'd RED.OR.
__global__ void __launch_bounds__(256)
k_prop_dense(const int* __restrict__ h, const int* __restrict__ t) {
    int i = blockIdx.x * 256 + threadIdx.x;
    if (i >= N_EDGES) return;
    int s = __ldg(h + i);
    int d = __ldg(t + i);
    ulonglong2 Ss = ldcg128(&g_state[s]);
    ulonglong2 Sd = ldcg128(&g_state[d]);
    if (Ss.x) { u64 nb = Ss.x & ~Sd.y; if (nb) atomicOr(&g_next[d], nb); }
    if (Sd.x) { u64 nb = Sd.x & ~Ss.y; if (nb) atomicOr(&g_next[s], nb); }
}

// ---------------------------------------------------------------------------
// Fold next -> {front, vis}, accumulate histogram byte, optionally rebuild the
// frontier bitmap (only consumed by the NEXT gated round, i.e. after round 1).
__global__ void __launch_bounds__(128)
k_update(int shift, int build_bm) {
    const int gw   = blockIdx.x * 4 + (threadIdx.x >> 5);  // global warp id
    const int lane = threadIdx.x & 31;
    const int n    = gw * 32 + lane;
    u64 nw = 0;
    if (n < N_ENT) {
        u64 nf = __ldcg(&g_next[n]);
        if (nf) {
            g_next[n] = 0ull;
            u64 v = __ldcg(&g_state[n].y);
            nw = nf & ~v;
            if (nw) {
                g_state[n] = make_ulonglong2(nw, v | nw);
                g_cnt[n]  += (u64)__popcll(nw) << shift;
            }
        }
    }
    if (build_bm) {
        u32 bal = __ballot_sync(0xffffffffu, nw != 0);
        if (lane == 0 && gw < NW32) g_Fbm[gw] = bal;
    }
}

// ---------------------------------------------------------------------------
// Depth-4 count + embedding combine, vectorized output.
__global__ void __launch_bounds__(256)
k_final(const float* __restrict__ embed, float* __restrict__ out) {
    __shared__ float sE[6 * D_PE];
    const int tid = threadIdx.x;
    if (tid < 6 * D_PE) sE[tid] = __ldg(embed + tid);
    __syncthreads();
    int n = blockIdx.x * 256 + tid;
    if (n >= N_ENT) return;

    u64 nf = __ldcg(&g_next[n]);
    u64 v  = __ldcg(&g_state[n].y);
    u64 c  = __ldcg(&g_cnt[n]);
    int c4 = __popcll(nf & ~v);
    int c0 = (int)( c        & 0xFF);
    int c1 = (int)((c >> 8)  & 0xFF);
    int c2 = (int)((c >> 16) & 0xFF);
    int c3 = (int)((c >> 24) & 0xFF);
    int nv = g_nvalid;
    int rem = nv - (c0 + c1 + c2 + c3 + c4);
    float inv = 1.0f / (float)nv;
    float w0 = c0 * inv, w1 = c1 * inv, w2 = c2 * inv;
    float w3 = c3 * inv, w4 = c4 * inv, w5 = rem * inv;

    float4* o = (float4*)(out + (size_t)n * D_PE);
#pragma unroll
    for (int q = 0; q < 4; q++) {
        float4 r;
        int b = q * 4;
        r.x = w0*sE[b+0] + w1*sE[D_PE+b+0] + w2*sE[2*D_PE+b+0]
            + w3*sE[3*D_PE+b+0] + w4*sE[4*D_PE+b+0] + w5*sE[5*D_PE+b+0];
        r.y = w0*sE[b+1] + w1*sE[D_PE+b+1] + w2*sE[2*D_PE+b+1]
            + w3*sE[3*D_PE+b+1] + w4*sE[4*D_PE+b+1] + w5*sE[5*D_PE+b+1];
        r.z = w0*sE[b+2] + w1*sE[D_PE+b+2] + w2*sE[2*D_PE+b+2]
            + w3*sE[3*D_PE+b+2] + w4*sE[4*D_PE+b+2] + w5*sE[5*D_PE+b+2];
        r.w = w0*sE[b+3] + w1*sE[D_PE+b+3] + w2*sE[2*D_PE+b+3]
            + w3*sE[3*D_PE+b+3] + w4*sE[4*D_PE+b+3] + w5*sE[5*D_PE+b+3];
        o[q] = r;
    }
}

// ---------------------------------------------------------------------------
extern "C" void kernel_launch(void* const* d_in, const int* in_sizes, int n_in,
                              void* d_out, int out_size) {
    const int*   h     = (const int*)d_in[0];   // [800000]
    const int*   t     = (const int*)d_in[1];   // [800000]
    const int*   aidx  = (const int*)d_in[2];   // [32]
    const float* embed = (const float*)d_in[4]; // [6,16]
    float*       out   = (float*)d_out;         // [50000,16]

    const int GN  = (N_ENT + 255) / 256;        // 196
    const int GU  = (N_ENT + 127) / 128;        // 391 (128-thread update blocks)
    const int GE2 = (N_EDGES + 511) / 512;      // 1563
    const int GE  = (N_EDGES + 255) / 256;      // 3125

    k_init<<<GN, 256>>>(h, t, aidx);

    // depth 1 (sparse, gated) -> update builds bitmap for depth 2
    k_prop_gated<<<GE2, 512>>>(h, t);
    k_update<<<GU, 128>>>(8 * 1, 1);

    // depth 2 (sparse, gated) -> no bitmap needed afterwards
    k_prop_gated<<<GE2, 512>>>(h, t);
    k_update<<<GU, 128>>>(8 * 2, 0);

    // depth 3 (dense)
    k_prop_dense<<<GE, 256>>>(h, t);
    k_update<<<GU, 128>>>(8 * 3, 0);

    // depth 4 (dense) + fused final
    k_prop_dense<<<GE, 256>>>(h, t);
    k_final<<<GN, 256>>>(embed, out);
}

// round 6
// speedup vs baseline: 1.8146x; 1.0069x over previous
#include <cuda_runtime.h>
#include <cstdint>

typedef unsigned long long u64;
typedef unsigned int u32;

#define N_ENT   50000
#define N_EDGES 800000
#define NQ      (N_EDGES/4)   // 200000 edge quads
#define D_PE    16
#define NW32    1564          // ceil(50000/32) rounded to even

// ---- device state (no allocations allowed) --------------------------------
__device__ ulonglong2 g_state[N_ENT];   // .x = frontier bits, .y = visited bits
__device__ u64 g_next[N_ENT];
__device__ u64 g_cnt[N_ENT];            // packed byte counts c0|c1<<8|c2<<16|c3<<24
__device__ u32 g_Fbm[NW32];             // frontier-nonempty bitmap (rounds 1-2)
__device__ int g_nvalid;

__device__ __forceinline__ ulonglong2 ldcg128(const ulonglong2* p) {
    ulonglong2 r;
    asm volatile("ld.global.cg.v2.u64 {%0,%1}, [%2];"
                 : "=l"(r.x), "=l"(r.y) : "l"(p));
    return r;
}

// ---------------------------------------------------------------------------
// Zero state + seed anchors (owner-block writes, ordered by __syncthreads).
__global__ void k_init(const int* __restrict__ h, const int* __restrict__ t,
                       const int* __restrict__ aidx) {
    __shared__ int svals[64];
    __shared__ int scnt;
    const int tid  = threadIdx.x;
    const int blk  = blockIdx.x;
    const int gtid = blk * 256 + tid;

    if (gtid < N_ENT) {
        g_state[gtid] = make_ulonglong2(0ull, 0ull);
        g_next[gtid]  = 0ull;
        g_cnt[gtid]   = 0ull;
    }
    if (tid < 8) {
        int w = blk * 8 + tid;
        if (w < NW32) g_Fbm[w] = 0u;
    }
    if (tid == 0) scnt = 0;
    if (tid < 64) {
        int e = __ldg(aidx + (tid & 31));
        svals[tid] = (tid < 32) ? __ldg(h + e) : __ldg(t + e);
    }
    __syncthreads();
    if (tid < 64) {
        int v = svals[tid];
        bool uniq = true;
        for (int j = 0; j < tid; j++) if (svals[j] == v) uniq = false;
        if (uniq) {
            if ((v >> 8) == blk) {
                u64 bit = 1ull << tid;
                g_state[v] = make_ulonglong2(bit, bit);
                g_cnt[v]   = 1ull;
                atomicOr(&g_Fbm[v >> 5], 1u << (v & 31));
            }
            if (blk == 0) atomicAdd(&scnt, 1);
        }
    }
    __syncthreads();
    if (blk == 0 && tid == 0) g_nvalid = scnt;
}

// ---------------------------------------------------------------------------
// Sparse rounds (1-2): 4 edges/thread; bitmap gathered via L1-resident __ldg
// (6.25 KB array). Live edges (rare) fall into the gather+atomic slow path.
__global__ void __launch_bounds__(256)
k_prop_gated(const int* __restrict__ h, const int* __restrict__ t) {
    int j = blockIdx.x * 256 + threadIdx.x;
    if (j >= NQ) return;
    int4 S = __ldg((const int4*)h + j);
    int4 D = __ldg((const int4*)t + j);

    // 8 independent L1-hit bitmap gathers (MLP batch)
    u32 wS0 = __ldg(&g_Fbm[S.x >> 5]), wD0 = __ldg(&g_Fbm[D.x >> 5]);
    u32 wS1 = __ldg(&g_Fbm[S.y >> 5]), wD1 = __ldg(&g_Fbm[D.y >> 5]);
    u32 wS2 = __ldg(&g_Fbm[S.z >> 5]), wD2 = __ldg(&g_Fbm[D.z >> 5]);
    u32 wS3 = __ldg(&g_Fbm[S.w >> 5]), wD3 = __ldg(&g_Fbm[D.w >> 5]);

    u32 f0 = ((wS0 >> (S.x & 31)) & 1u) | (((wD0 >> (D.x & 31)) & 1u) << 1);
    u32 f1 = ((wS1 >> (S.y & 31)) & 1u) | (((wD1 >> (D.y & 31)) & 1u) << 1);
    u32 f2 = ((wS2 >> (S.z & 31)) & 1u) | (((wD2 >> (D.z & 31)) & 1u) << 1);
    u32 f3 = ((wS3 >> (S.w & 31)) & 1u) | (((wD3 >> (D.w & 31)) & 1u) << 1);

    if (f0) {
        ulonglong2 a = ldcg128(&g_state[S.x]), b = ldcg128(&g_state[D.x]);
        if (f0 & 1) { u64 nb = a.x & ~b.y; if (nb) atomicOr(&g_next[D.x], nb); }
        if (f0 & 2) { u64 nb = b.x & ~a.y; if (nb) atomicOr(&g_next[S.x], nb); }
    }
    if (f1) {
        ulonglong2 a = ldcg128(&g_state[S.y]), b = ldcg128(&g_state[D.y]);
        if (f1 & 1) { u64 nb = a.x & ~b.y; if (nb) atomicOr(&g_next[D.y], nb); }
        if (f1 & 2) { u64 nb = b.x & ~a.y; if (nb) atomicOr(&g_next[S.y], nb); }
    }
    if (f2) {
        ulonglong2 a = ldcg128(&g_state[S.z]), b = ldcg128(&g_state[D.z]);
        if (f2 & 1) { u64 nb = a.x & ~b.y; if (nb) atomicOr(&g_next[D.z], nb); }
        if (f2 & 2) { u64 nb = b.x & ~a.y; if (nb) atomicOr(&g_next[S.z], nb); }
    }
    if (f3) {
        ulonglong2 a = ldcg128(&g_state[S.w]), b = ldcg128(&g_state[D.w]);
        if (f3 & 1) { u64 nb = a.x & ~b.y; if (nb) atomicOr(&g_next[D.w], nb); }
        if (f3 & 2) { u64 nb = b.x & ~a.y; if (nb) atomicOr(&g_next[S.w], nb); }
    }
}

// ---------------------------------------------------------------------------
// Dense rounds (3-4): 4 edges/thread, 8 unconditional MLP-batched 16B gathers,
// dedup'd conditional atomics.
__global__ void __launch_bounds__(256)
k_prop_dense(const int* __restrict__ h, const int* __restrict__ t) {
    int j = blockIdx.x * 256 + threadIdx.x;
    if (j >= NQ) return;
    int4 S = __ldg((const int4*)h + j);
    int4 D = __ldg((const int4*)t + j);

    ulonglong2 a0 = ldcg128(&g_state[S.x]);
    ulonglong2 b0 = ldcg128(&g_state[D.x]);
    ulonglong2 a1 = ldcg128(&g_state[S.y]);
    ulonglong2 b1 = ldcg128(&g_state[D.y]);
    ulonglong2 a2 = ldcg128(&g_state[S.z]);
    ulonglong2 b2 = ldcg128(&g_state[D.z]);
    ulonglong2 a3 = ldcg128(&g_state[S.w]);
    ulonglong2 b3 = ldcg128(&g_state[D.w]);

    u64 nb;
    nb = a0.x & ~b0.y; if (nb) atomicOr(&g_next[D.x], nb);
    nb = b0.x & ~a0.y; if (nb) atomicOr(&g_next[S.x], nb);
    nb = a1.x & ~b1.y; if (nb) atomicOr(&g_next[D.y], nb);
    nb = b1.x & ~a1.y; if (nb) atomicOr(&g_next[S.y], nb);
    nb = a2.x & ~b2.y; if (nb) atomicOr(&g_next[D.z], nb);
    nb = b2.x & ~a2.y; if (nb) atomicOr(&g_next[S.z], nb);
    nb = a3.x & ~b3.y; if (nb) atomicOr(&g_next[D.w], nb);
    nb = b3.x & ~a3.y; if (nb) atomicOr(&g_next[S.w], nb);
}

// ---------------------------------------------------------------------------
// Fold next -> {front, vis}; rebuild bitmap only when next round is gated.
__global__ void __launch_bounds__(256)
k_update(int shift, int build_bm) {
    const int gw   = blockIdx.x * 8 + (threadIdx.x >> 5);
    const int lane = threadIdx.x & 31;
    const int n    = gw * 32 + lane;
    u64 nw = 0;
    if (n < N_ENT) {
        u64 nf = __ldcg(&g_next[n]);
        if (nf) {
            g_next[n] = 0ull;
            u64 v = __ldcg(&g_state[n].y);
            nw = nf & ~v;
            if (nw) {
                g_state[n] = make_ulonglong2(nw, v | nw);
                g_cnt[n]  += (u64)__popcll(nw) << shift;
            }
        }
    }
    if (build_bm) {
        u32 bal = __ballot_sync(0xffffffffu, nw != 0);
        if (lane == 0 && gw < NW32) g_Fbm[gw] = bal;
    }
}

// ---------------------------------------------------------------------------
// Depth-4 count + embedding combine.
__global__ void __launch_bounds__(256)
k_final(const float* __restrict__ embed, float* __restrict__ out) {
    __shared__ float sE[6 * D_PE];
    const int tid = threadIdx.x;
    if (tid < 6 * D_PE) sE[tid] = __ldg(embed + tid);
    __syncthreads();
    int n = blockIdx.x * 256 + tid;
    if (n >= N_ENT) return;

    u64 nf = __ldcg(&g_next[n]);
    u64 v  = __ldcg(&g_state[n].y);
    u64 c  = __ldcg(&g_cnt[n]);
    int c4 = __popcll(nf & ~v);
    int c0 = (int)( c        & 0xFF);
    int c1 = (int)((c >> 8)  & 0xFF);
    int c2 = (int)((c >> 16) & 0xFF);
    int c3 = (int)((c >> 24) & 0xFF);
    int nv = g_nvalid;
    int rem = nv - (c0 + c1 + c2 + c3 + c4);
    float inv = 1.0f / (float)nv;
    float w0 = c0 * inv, w1 = c1 * inv, w2 = c2 * inv;
    float w3 = c3 * inv, w4 = c4 * inv, w5 = rem * inv;

    float4* o = (float4*)(out + (size_t)n * D_PE);
#pragma unroll
    for (int q = 0; q < 4; q++) {
        float4 r;
        int b = q * 4;
        r.x = w0*sE[b+0] + w1*sE[D_PE+b+0] + w2*sE[2*D_PE+b+0]
            + w3*sE[3*D_PE+b+0] + w4*sE[4*D_PE+b+0] + w5*sE[5*D_PE+b+0];
        r.y = w0*sE[b+1] + w1*sE[D_PE+b+1] + w2*sE[2*D_PE+b+1]
            + w3*sE[3*D_PE+b+1] + w4*sE[4*D_PE+b+1] + w5*sE[5*D_PE+b+1];
        r.z = w0*sE[b+2] + w1*sE[D_PE+b+2] + w2*sE[2*D_PE+b+2]
            + w3*sE[3*D_PE+b+2] + w4*sE[4*D_PE+b+2] + w5*sE[5*D_PE+b+2];
        r.w = w0*sE[b+3] + w1*sE[D_PE+b+3] + w2*sE[2*D_PE+b+3]
            + w3*sE[3*D_PE+b+3] + w4*sE[4*D_PE+b+3] + w5*sE[5*D_PE+b+3];
        o[q] = r;
    }
}

// ---------------------------------------------------------------------------
extern "C" void kernel_launch(void* const* d_in, const int* in_sizes, int n_in,
                              void* d_out, int out_size) {
    const int*   h     = (const int*)d_in[0];   // [800000]
    const int*   t     = (const int*)d_in[1];   // [800000]
    const int*   aidx  = (const int*)d_in[2];   // [32]
    const float* embed = (const float*)d_in[4]; // [6,16]
    float*       out   = (float*)d_out;         // [50000,16]

    const int GN = (N_ENT + 255) / 256;   // 196
    const int GU = (N_ENT + 8*32 - 1) / (8*32); // 196 (256-thr, 8 warps)
    const int GQ = (NQ + 255) / 256;      // 782

    k_init<<<GN, 256>>>(h, t, aidx);

    k_prop_gated<<<GQ, 256>>>(h, t);      // depth 1 (sparse)
    k_update<<<GU, 256>>>(8 * 1, 1);      // build bitmap for depth 2

    k_prop_gated<<<GQ, 256>>>(h, t);      // depth 2 (sparse)
    k_update<<<GU, 256>>>(8 * 2, 0);

    k_prop_dense<<<GQ, 256>>>(h, t);      // depth 3 (dense)
    k_update<<<GU, 256>>>(8 * 3, 0);

    k_prop_dense<<<GQ, 256>>>(h, t);      // depth 4 (dense)
    k_final<<<GN, 256>>>(embed, out);     // fused depth-4 count + output
}